// round 1
// baseline (speedup 1.0000x reference)
#include <cuda_runtime.h>
#include <math.h>

#define BB 64
#define TT 4096
#define DD 90
#define KK 32
#define LOG2PI_F 1.8378770664093453f
#define TILE_T 32
#define FULLMASK 0xffffffffu

// ---- scratch (no allocations allowed; __device__ globals) ----
__device__ __align__(16) float g_eexp[BB * TT * KK];   // exp(em - emax), 33.5 MB
__device__ float g_emax[BB * TT];                       // per (b,t) max_k em
__device__ __align__(16) float g_w1t[DD * KK];          // [d][k] = -0.5*inv_var
__device__ __align__(16) float g_w2t[DD * KK];          // [d][k] = mu*inv_var
__device__ __align__(16) float g_bias[KK];
__device__ float g_pi[KK];                              // softmax(state_priors)
__device__ float g_expA[KK * KK];                       // row-softmax(transition)
__device__ float g_partial[BB];

__device__ __forceinline__ float warpMax(float v) {
#pragma unroll
    for (int o = 16; o > 0; o >>= 1) v = fmaxf(v, __shfl_xor_sync(FULLMASK, v, o));
    return v;
}
__device__ __forceinline__ float warpSum(float v) {
#pragma unroll
    for (int o = 16; o > 0; o >>= 1) v += __shfl_xor_sync(FULLMASK, v, o);
    return v;
}

// ---------------------------------------------------------------------------
// Kernel 1: prep — softmaxes + emission coefficients (tiny, one block)
// ---------------------------------------------------------------------------
__global__ void hmm_prep_kernel(const float* __restrict__ sp,
                                const float* __restrict__ trans,
                                const float* __restrict__ mu,
                                const float* __restrict__ log_var) {
    int tid = threadIdx.x, wid = tid >> 5, lane = tid & 31;

    // pi = softmax(state_priors)  (warp 0)
    if (wid == 0) {
        float v = sp[lane];
        float m = warpMax(v);
        float e = expf(v - m);
        float s = warpSum(e);
        g_pi[lane] = e / s;
    }

    // expA row wid = softmax(transition_matrix[wid, :])   (32 warps)
    {
        float v = trans[wid * KK + lane];
        float m = warpMax(v);
        float e = expf(v - m);
        float s = warpSum(e);
        g_expA[wid * KK + lane] = e / s;
    }

    // transposed emission weights [d][k]
    for (int o = tid; o < DD * KK; o += blockDim.x) {
        int d = o >> 5, k = o & 31;
        float lv = log_var[k * DD + d];
        float iv = expf(-lv);
        g_w1t[o] = -0.5f * iv;
        g_w2t[o] = mu[k * DD + d] * iv;
    }

    // bias[k] = -0.5*(sum_d mu^2*iv + sum_d log_var + D*log(2pi)); warp wid -> k
    {
        int k = wid;
        float acc = 0.0f;
        for (int d = lane; d < DD; d += 32) {
            float lv = log_var[k * DD + d];
            float iv = expf(-lv);
            float m = mu[k * DD + d];
            acc = fmaf(m * m, iv, acc + lv);
        }
        acc = warpSum(acc);
        if (lane == 0) g_bias[k] = -0.5f * (acc + (float)DD * LOG2PI_F);
    }
}

// ---------------------------------------------------------------------------
// Kernel 2: emissions -> scaled probabilities eexp + emax
// block = 256 threads handles TILE_T=32 flattened timesteps; thread = (t, 4 k's)
// ---------------------------------------------------------------------------
__global__ void hmm_emis_kernel(const float* __restrict__ X) {
    __shared__ __align__(16) float xs[TILE_T * DD];
    __shared__ __align__(16) float w1s[DD * KK];
    __shared__ __align__(16) float w2s[DD * KK];

    int tid = threadIdx.x;
    long base = (long)blockIdx.x * TILE_T;  // flattened (b*T + t) start

    for (int i = tid; i < TILE_T * DD; i += 256) xs[i] = X[base * DD + i];
    for (int i = tid; i < DD * KK; i += 256) { w1s[i] = g_w1t[i]; w2s[i] = g_w2t[i]; }
    __syncthreads();

    int tl = tid >> 3;   // 0..31 local timestep
    int kg = tid & 7;    // 0..7 -> k group of 4
    int k0 = kg * 4;

    float a0 = 0.f, a1 = 0.f, a2 = 0.f, a3 = 0.f;
    const float* xr = &xs[tl * DD];
#pragma unroll 6
    for (int d = 0; d < DD; ++d) {
        float x = xr[d];
        float xx = x * x;
        float4 w1 = *(const float4*)&w1s[d * KK + k0];
        float4 w2 = *(const float4*)&w2s[d * KK + k0];
        a0 = fmaf(w1.x, xx, fmaf(w2.x, x, a0));
        a1 = fmaf(w1.y, xx, fmaf(w2.y, x, a1));
        a2 = fmaf(w1.z, xx, fmaf(w2.z, x, a2));
        a3 = fmaf(w1.w, xx, fmaf(w2.w, x, a3));
    }
    float4 bv = *(const float4*)&g_bias[k0];
    float e0 = a0 + bv.x, e1 = a1 + bv.y, e2 = a2 + bv.z, e3 = a3 + bv.w;

    float m = fmaxf(fmaxf(e0, e1), fmaxf(e2, e3));
    m = fmaxf(m, __shfl_xor_sync(FULLMASK, m, 1));
    m = fmaxf(m, __shfl_xor_sync(FULLMASK, m, 2));
    m = fmaxf(m, __shfl_xor_sync(FULLMASK, m, 4));

    long bt = base + tl;
    float4 out;
    out.x = __expf(e0 - m);
    out.y = __expf(e1 - m);
    out.z = __expf(e2 - m);
    out.w = __expf(e3 - m);
    *(float4*)&g_eexp[bt * KK + k0] = out;
    if (kg == 0) g_emax[bt] = m;
}

// ---------------------------------------------------------------------------
// Kernel 3: forward scan, one warp per batch; lane = state k.
// Probability domain with precomputed scaling; renorm every 16 steps.
// ---------------------------------------------------------------------------
__global__ void hmm_scan_kernel() {
    int b = blockIdx.x;
    int k = threadIdx.x;
    const float* __restrict__ erow = &g_eexp[(long)b * TT * KK];
    const float* __restrict__ emaxr = &g_emax[(long)b * TT];

    float Acol[KK];
#pragma unroll
    for (int j = 0; j < KK; ++j) Acol[j] = g_expA[j * KK + k];

    float u = g_pi[k] * erow[k];          // t = 0
    double logZ = (double)emaxr[0];

    float e_cur = erow[KK + k];           // t = 1 prefetched
    float emax_cur = emaxr[1];

    for (int t = 1; t < TT; ++t) {
        int tn = (t + 1 < TT) ? (t + 1) : t;
        float e_next = erow[tn * KK + k];
        float emax_next = emaxr[tn];

        float s0 = 0.f, s1 = 0.f, s2 = 0.f, s3 = 0.f;
#pragma unroll
        for (int j = 0; j < KK; j += 4) {
            s0 = fmaf(__shfl_sync(FULLMASK, u, j + 0), Acol[j + 0], s0);
            s1 = fmaf(__shfl_sync(FULLMASK, u, j + 1), Acol[j + 1], s1);
            s2 = fmaf(__shfl_sync(FULLMASK, u, j + 2), Acol[j + 2], s2);
            s3 = fmaf(__shfl_sync(FULLMASK, u, j + 3), Acol[j + 3], s3);
        }
        float unew = e_cur * ((s0 + s1) + (s2 + s3));
        logZ += (double)emax_cur;

        if ((t & 15) == 0) {              // renorm (step-sum >= 1/(32e) => safe)
            float S = warpSum(unew);
            unew = unew / S;
            logZ += (double)logf(S);
        }
        u = unew;
        e_cur = e_next;
        emax_cur = emax_next;
    }
    float S = warpSum(u);
    if (k == 0) g_partial[b] = (float)(logZ + (double)logf(S));
}

// ---------------------------------------------------------------------------
// Kernel 4: reduce 64 per-batch results to scalar
// ---------------------------------------------------------------------------
__global__ void hmm_final_kernel(float* __restrict__ out) {
    int lane = threadIdx.x;
    float v = g_partial[lane] + g_partial[lane + 32];
    v = warpSum(v);
    if (lane == 0) out[0] = v;
}

// ---------------------------------------------------------------------------
extern "C" void kernel_launch(void* const* d_in, const int* in_sizes, int n_in,
                              void* d_out, int out_size) {
    const float* X = (const float*)d_in[0];
    const float* sp = (const float*)d_in[1];
    const float* trans = (const float*)d_in[2];
    const float* mu = (const float*)d_in[3];
    const float* log_var = (const float*)d_in[4];

    hmm_prep_kernel<<<1, 1024>>>(sp, trans, mu, log_var);
    hmm_emis_kernel<<<(BB * TT) / TILE_T, 256>>>(X);
    hmm_scan_kernel<<<BB, KK>>>();
    hmm_final_kernel<<<1, 32>>>((float*)d_out);
}

// round 2
// speedup vs baseline: 2.9897x; 2.9897x over previous
#include <cuda_runtime.h>
#include <math.h>

#define BB 64
#define TT 4096
#define DD 90
#define KK 32
#define LOG2PI_F 1.8378770664093453f
#define FULLMASK 0xffffffffu

// ---- scratch (__device__ globals; no allocations allowed) ----
__device__ __align__(16) float g_eexp[BB * TT * KK];   // exp(em - emax)
__device__ float g_emax[BB * TT];                       // per (b,t) max_k em
__device__ float g_emaxsum[BB];                         // per-b sum of emax
__device__ __align__(16) float g_w1t[DD * KK];          // [d][k] = -0.5*inv_var
__device__ __align__(16) float g_w2t[DD * KK];          // [d][k] = mu*inv_var
__device__ __align__(16) float g_bias[KK];
__device__ float g_pi[KK];
__device__ float g_expA[KK * KK];
__device__ float g_partial[BB];

__device__ __forceinline__ float warpMax(float v) {
#pragma unroll
    for (int o = 16; o > 0; o >>= 1) v = fmaxf(v, __shfl_xor_sync(FULLMASK, v, o));
    return v;
}
__device__ __forceinline__ float warpSum(float v) {
#pragma unroll
    for (int o = 16; o > 0; o >>= 1) v += __shfl_xor_sync(FULLMASK, v, o);
    return v;
}

// ---------------------------------------------------------------------------
// Kernel 1: prep — softmaxes + emission coefficients
// ---------------------------------------------------------------------------
__global__ void hmm_prep_kernel(const float* __restrict__ sp,
                                const float* __restrict__ trans,
                                const float* __restrict__ mu,
                                const float* __restrict__ log_var) {
    int tid = threadIdx.x, wid = tid >> 5, lane = tid & 31;

    if (wid == 0) {
        float v = sp[lane];
        float m = warpMax(v);
        float e = expf(v - m);
        float s = warpSum(e);
        g_pi[lane] = e / s;
    }
    {
        float v = trans[wid * KK + lane];
        float m = warpMax(v);
        float e = expf(v - m);
        float s = warpSum(e);
        g_expA[wid * KK + lane] = e / s;
    }
    for (int o = tid; o < DD * KK; o += blockDim.x) {
        int d = o >> 5, k = o & 31;
        float lv = log_var[k * DD + d];
        float iv = expf(-lv);
        g_w1t[o] = -0.5f * iv;
        g_w2t[o] = mu[k * DD + d] * iv;
    }
    {
        int k = wid;
        float acc = 0.0f;
        for (int d = lane; d < DD; d += 32) {
            float lv = log_var[k * DD + d];
            float iv = expf(-lv);
            float m = mu[k * DD + d];
            acc = fmaf(m * m, iv, acc + lv);
        }
        acc = warpSum(acc);
        if (lane == 0) g_bias[k] = -0.5f * (acc + (float)DD * LOG2PI_F);
    }
}

// ---------------------------------------------------------------------------
// Kernel 2: emissions v2 — 64 timesteps/block, thread = (2 t's) x (4 k's)
// FMA-issue bound: per d, 2x LDS.128 weights amortized over 2 timesteps.
// ---------------------------------------------------------------------------
#define TILE_T2 64
__global__ void hmm_emis_kernel(const float* __restrict__ X) {
    __shared__ __align__(16) float xs[TILE_T2 * DD];      // 23 KB
    __shared__ __align__(16) float w1s[DD * KK];          // 11.25 KB
    __shared__ __align__(16) float w2s[DD * KK];          // 11.25 KB

    int tid = threadIdx.x;
    long base = (long)blockIdx.x * TILE_T2;               // flattened (b*T+t)

    {   // vectorized staging
        const float4* X4 = (const float4*)(X + base * DD);
        float4* xs4 = (float4*)xs;
        for (int i = tid; i < TILE_T2 * DD / 4; i += 256) xs4[i] = X4[i];
        const float4* w14 = (const float4*)g_w1t;
        const float4* w24 = (const float4*)g_w2t;
        float4* w1s4 = (float4*)w1s;
        float4* w2s4 = (float4*)w2s;
        for (int i = tid; i < DD * KK / 4; i += 256) { w1s4[i] = w14[i]; w2s4[i] = w24[i]; }
    }
    __syncthreads();

    int kq = tid & 7;            // k group of 4
    int tq = tid >> 3;           // 0..31
    int k0 = kq * 4;
    int t0 = tq * 2, t1 = t0 + 1;

    float a00 = 0.f, a01 = 0.f, a02 = 0.f, a03 = 0.f;
    float a10 = 0.f, a11 = 0.f, a12 = 0.f, a13 = 0.f;
    const float* xr0 = &xs[t0 * DD];
    const float* xr1 = &xs[t1 * DD];
#pragma unroll 3
    for (int d = 0; d < DD; ++d) {
        float4 w1 = *(const float4*)&w1s[d * KK + k0];
        float4 w2 = *(const float4*)&w2s[d * KK + k0];
        float x0 = xr0[d], x1 = xr1[d];
        float xx0 = x0 * x0, xx1 = x1 * x1;
        a00 = fmaf(w1.x, xx0, fmaf(w2.x, x0, a00));
        a01 = fmaf(w1.y, xx0, fmaf(w2.y, x0, a01));
        a02 = fmaf(w1.z, xx0, fmaf(w2.z, x0, a02));
        a03 = fmaf(w1.w, xx0, fmaf(w2.w, x0, a03));
        a10 = fmaf(w1.x, xx1, fmaf(w2.x, x1, a10));
        a11 = fmaf(w1.y, xx1, fmaf(w2.y, x1, a11));
        a12 = fmaf(w1.z, xx1, fmaf(w2.z, x1, a12));
        a13 = fmaf(w1.w, xx1, fmaf(w2.w, x1, a13));
    }
    float4 bv = *(const float4*)&g_bias[k0];
    float e00 = a00 + bv.x, e01 = a01 + bv.y, e02 = a02 + bv.z, e03 = a03 + bv.w;
    float e10 = a10 + bv.x, e11 = a11 + bv.y, e12 = a12 + bv.z, e13 = a13 + bv.w;

    // max over k (8 lanes with same tq are consecutive -> xor 1,2,4)
    float m0 = fmaxf(fmaxf(e00, e01), fmaxf(e02, e03));
    float m1 = fmaxf(fmaxf(e10, e11), fmaxf(e12, e13));
#pragma unroll
    for (int o = 1; o <= 4; o <<= 1) {
        m0 = fmaxf(m0, __shfl_xor_sync(FULLMASK, m0, o));
        m1 = fmaxf(m1, __shfl_xor_sync(FULLMASK, m1, o));
    }

    long bt0 = base + t0, bt1 = base + t1;
    float4 o0, o1;
    o0.x = __expf(e00 - m0); o0.y = __expf(e01 - m0);
    o0.z = __expf(e02 - m0); o0.w = __expf(e03 - m0);
    o1.x = __expf(e10 - m1); o1.y = __expf(e11 - m1);
    o1.z = __expf(e12 - m1); o1.w = __expf(e13 - m1);
    *(float4*)&g_eexp[bt0 * KK + k0] = o0;
    *(float4*)&g_eexp[bt1 * KK + k0] = o1;
    if (kq == 0) { g_emax[bt0] = m0; g_emax[bt1] = m1; }
}

// ---------------------------------------------------------------------------
// Kernel 3: per-batch sum of emax (order-independent piece of logZ)
// ---------------------------------------------------------------------------
__global__ void hmm_emaxsum_kernel() {
    __shared__ float red[8];
    int b = blockIdx.x, tid = threadIdx.x;
    const float* r = &g_emax[(long)b * TT];
    float s = 0.f;
    for (int t = tid; t < TT; t += 256) s += r[t];
    s = warpSum(s);
    if ((tid & 31) == 0) red[tid >> 5] = s;
    __syncthreads();
    if (tid < 8) {
        float v = red[tid];
#pragma unroll
        for (int o = 4; o > 0; o >>= 1) v += __shfl_xor_sync(0xff, v, o);
        if (tid == 0) g_emaxsum[b] = v;
    }
}

// ---------------------------------------------------------------------------
// Kernel 4: forward scan, 1 warp/batch, 16-step double-buffered prefetch.
// ---------------------------------------------------------------------------
__global__ void hmm_scan_kernel() {
    int b = blockIdx.x;
    int k = threadIdx.x;
    const float* __restrict__ erow = &g_eexp[(long)b * TT * KK];

    float Acol[KK];
#pragma unroll
    for (int j = 0; j < KK; ++j) Acol[j] = g_expA[j * KK + k];

    float u = g_pi[k] * erow[k];          // t = 0
    double logZ = 0.0;

    float bufA[16], bufB[16];
#pragma unroll
    for (int i = 0; i < 16; ++i) bufA[i] = erow[(1 + i) * KK + k];   // t=1..16

    int t = 1;
    for (int tb = 0; tb < 255; ++tb) {
        int nb = t + 16;                  // prefetch t+16 .. t+31
#pragma unroll
        for (int i = 0; i < 16; ++i)
            bufB[i] = (nb + i < TT) ? erow[(long)(nb + i) * KK + k] : 0.f;

#pragma unroll
        for (int i = 0; i < 16; ++i) {
            float s0 = 0.f, s1 = 0.f, s2 = 0.f, s3 = 0.f;
#pragma unroll
            for (int j = 0; j < KK; j += 4) {
                s0 = fmaf(__shfl_sync(FULLMASK, u, j + 0), Acol[j + 0], s0);
                s1 = fmaf(__shfl_sync(FULLMASK, u, j + 1), Acol[j + 1], s1);
                s2 = fmaf(__shfl_sync(FULLMASK, u, j + 2), Acol[j + 2], s2);
                s3 = fmaf(__shfl_sync(FULLMASK, u, j + 3), Acol[j + 3], s3);
            }
            u = bufA[i] * ((s0 + s1) + (s2 + s3));
            if (i == 15) {                // renorm every 16 steps
                float S = warpSum(u);
                u = u / S;
                logZ += (double)__logf(S);
            }
        }
        t += 16;
#pragma unroll
        for (int i = 0; i < 16; ++i) bufA[i] = bufB[i];
    }
    // tail: t = 4081 .. 4095 (15 steps) already in bufA
#pragma unroll
    for (int i = 0; i < 15; ++i) {
        float s0 = 0.f, s1 = 0.f, s2 = 0.f, s3 = 0.f;
#pragma unroll
        for (int j = 0; j < KK; j += 4) {
            s0 = fmaf(__shfl_sync(FULLMASK, u, j + 0), Acol[j + 0], s0);
            s1 = fmaf(__shfl_sync(FULLMASK, u, j + 1), Acol[j + 1], s1);
            s2 = fmaf(__shfl_sync(FULLMASK, u, j + 2), Acol[j + 2], s2);
            s3 = fmaf(__shfl_sync(FULLMASK, u, j + 3), Acol[j + 3], s3);
        }
        u = bufA[i] * ((s0 + s1) + (s2 + s3));
    }
    float S = warpSum(u);
    if (k == 0) g_partial[b] = (float)(logZ + (double)logf(S));
}

// ---------------------------------------------------------------------------
// Kernel 5: final scalar
// ---------------------------------------------------------------------------
__global__ void hmm_final_kernel(float* __restrict__ out) {
    int lane = threadIdx.x;
    float v = g_partial[lane] + g_partial[lane + 32]
            + g_emaxsum[lane] + g_emaxsum[lane + 32];
    v = warpSum(v);
    if (lane == 0) out[0] = v;
}

// ---------------------------------------------------------------------------
extern "C" void kernel_launch(void* const* d_in, const int* in_sizes, int n_in,
                              void* d_out, int out_size) {
    const float* X = (const float*)d_in[0];
    const float* sp = (const float*)d_in[1];
    const float* trans = (const float*)d_in[2];
    const float* mu = (const float*)d_in[3];
    const float* log_var = (const float*)d_in[4];

    hmm_prep_kernel<<<1, 1024>>>(sp, trans, mu, log_var);
    hmm_emis_kernel<<<(BB * TT) / TILE_T2, 256>>>(X);
    hmm_emaxsum_kernel<<<BB, 256>>>();
    hmm_scan_kernel<<<BB, KK>>>();
    hmm_final_kernel<<<1, 32>>>((float*)d_out);
}

// round 3
// speedup vs baseline: 10.2148x; 3.4166x over previous
#include <cuda_runtime.h>
#include <math.h>

#define BB 64
#define TT 4096
#define DD 90
#define KK 32
#define CC 32            // chunks per batch
#define CHUNK 128        // TT / CC
#define WARM 64          // burn-in steps (contraction 0.46^64 ~ 1e-21)
#define LOG2PI_F 1.8378770664093453f
#define FULLMASK 0xffffffffu

// ---- scratch (__device__ globals; no allocations allowed) ----
__device__ __align__(16) float g_eexp[BB * TT * KK];   // exp(em - emax)
__device__ float g_emax[BB * TT];                       // per (b,t) max_k em
__device__ float g_emaxsum[BB];                         // per-b sum of emax
__device__ __align__(16) float g_w1t[DD * KK];          // [d][k] = -0.5*inv_var
__device__ __align__(16) float g_w2t[DD * KK];          // [d][k] = mu*inv_var
__device__ __align__(16) float g_bias[KK];
__device__ float g_pi[KK];
__device__ float g_expA[KK * KK];
__device__ float g_partial2[BB * CC];                   // per (b, chunk) log factor

__device__ __forceinline__ float warpMax(float v) {
#pragma unroll
    for (int o = 16; o > 0; o >>= 1) v = fmaxf(v, __shfl_xor_sync(FULLMASK, v, o));
    return v;
}
__device__ __forceinline__ float warpSum(float v) {
#pragma unroll
    for (int o = 16; o > 0; o >>= 1) v += __shfl_xor_sync(FULLMASK, v, o);
    return v;
}

// ---------------------------------------------------------------------------
// Kernel 1: prep — softmaxes + emission coefficients
// ---------------------------------------------------------------------------
__global__ void hmm_prep_kernel(const float* __restrict__ sp,
                                const float* __restrict__ trans,
                                const float* __restrict__ mu,
                                const float* __restrict__ log_var) {
    int tid = threadIdx.x, wid = tid >> 5, lane = tid & 31;

    if (wid == 0) {
        float v = sp[lane];
        float m = warpMax(v);
        float e = expf(v - m);
        float s = warpSum(e);
        g_pi[lane] = e / s;
    }
    {
        float v = trans[wid * KK + lane];
        float m = warpMax(v);
        float e = expf(v - m);
        float s = warpSum(e);
        g_expA[wid * KK + lane] = e / s;
    }
    for (int o = tid; o < DD * KK; o += blockDim.x) {
        int d = o >> 5, k = o & 31;
        float lv = log_var[k * DD + d];
        float iv = expf(-lv);
        g_w1t[o] = -0.5f * iv;
        g_w2t[o] = mu[k * DD + d] * iv;
    }
    {
        int k = wid;
        float acc = 0.0f;
        for (int d = lane; d < DD; d += 32) {
            float lv = log_var[k * DD + d];
            float iv = expf(-lv);
            float m = mu[k * DD + d];
            acc = fmaf(m * m, iv, acc + lv);
        }
        acc = warpSum(acc);
        if (lane == 0) g_bias[k] = -0.5f * (acc + (float)DD * LOG2PI_F);
    }
}

// ---------------------------------------------------------------------------
// Kernel 2: emissions — 64 timesteps/block, thread = (2 t's) x (4 k's)
// ---------------------------------------------------------------------------
#define TILE_T2 64
__global__ void hmm_emis_kernel(const float* __restrict__ X) {
    __shared__ __align__(16) float xs[TILE_T2 * DD];
    __shared__ __align__(16) float w1s[DD * KK];
    __shared__ __align__(16) float w2s[DD * KK];

    int tid = threadIdx.x;
    long base = (long)blockIdx.x * TILE_T2;

    {
        const float4* X4 = (const float4*)(X + base * DD);
        float4* xs4 = (float4*)xs;
        for (int i = tid; i < TILE_T2 * DD / 4; i += 256) xs4[i] = X4[i];
        const float4* w14 = (const float4*)g_w1t;
        const float4* w24 = (const float4*)g_w2t;
        float4* w1s4 = (float4*)w1s;
        float4* w2s4 = (float4*)w2s;
        for (int i = tid; i < DD * KK / 4; i += 256) { w1s4[i] = w14[i]; w2s4[i] = w24[i]; }
    }
    __syncthreads();

    int kq = tid & 7;
    int tq = tid >> 3;
    int k0 = kq * 4;
    int t0 = tq * 2, t1 = t0 + 1;

    float a00 = 0.f, a01 = 0.f, a02 = 0.f, a03 = 0.f;
    float a10 = 0.f, a11 = 0.f, a12 = 0.f, a13 = 0.f;
    const float* xr0 = &xs[t0 * DD];
    const float* xr1 = &xs[t1 * DD];
#pragma unroll 3
    for (int d = 0; d < DD; ++d) {
        float4 w1 = *(const float4*)&w1s[d * KK + k0];
        float4 w2 = *(const float4*)&w2s[d * KK + k0];
        float x0 = xr0[d], x1 = xr1[d];
        float xx0 = x0 * x0, xx1 = x1 * x1;
        a00 = fmaf(w1.x, xx0, fmaf(w2.x, x0, a00));
        a01 = fmaf(w1.y, xx0, fmaf(w2.y, x0, a01));
        a02 = fmaf(w1.z, xx0, fmaf(w2.z, x0, a02));
        a03 = fmaf(w1.w, xx0, fmaf(w2.w, x0, a03));
        a10 = fmaf(w1.x, xx1, fmaf(w2.x, x1, a10));
        a11 = fmaf(w1.y, xx1, fmaf(w2.y, x1, a11));
        a12 = fmaf(w1.z, xx1, fmaf(w2.z, x1, a12));
        a13 = fmaf(w1.w, xx1, fmaf(w2.w, x1, a13));
    }
    float4 bv = *(const float4*)&g_bias[k0];
    float e00 = a00 + bv.x, e01 = a01 + bv.y, e02 = a02 + bv.z, e03 = a03 + bv.w;
    float e10 = a10 + bv.x, e11 = a11 + bv.y, e12 = a12 + bv.z, e13 = a13 + bv.w;

    float m0 = fmaxf(fmaxf(e00, e01), fmaxf(e02, e03));
    float m1 = fmaxf(fmaxf(e10, e11), fmaxf(e12, e13));
#pragma unroll
    for (int o = 1; o <= 4; o <<= 1) {
        m0 = fmaxf(m0, __shfl_xor_sync(FULLMASK, m0, o));
        m1 = fmaxf(m1, __shfl_xor_sync(FULLMASK, m1, o));
    }

    long bt0 = base + t0, bt1 = base + t1;
    float4 o0, o1;
    o0.x = __expf(e00 - m0); o0.y = __expf(e01 - m0);
    o0.z = __expf(e02 - m0); o0.w = __expf(e03 - m0);
    o1.x = __expf(e10 - m1); o1.y = __expf(e11 - m1);
    o1.z = __expf(e12 - m1); o1.w = __expf(e13 - m1);
    *(float4*)&g_eexp[bt0 * KK + k0] = o0;
    *(float4*)&g_eexp[bt1 * KK + k0] = o1;
    if (kq == 0) { g_emax[bt0] = m0; g_emax[bt1] = m1; }
}

// ---------------------------------------------------------------------------
// Kernel 3: per-batch sum of emax (order-independent piece of logZ)
// ---------------------------------------------------------------------------
__global__ void hmm_emaxsum_kernel() {
    __shared__ float red[8];
    int b = blockIdx.x, tid = threadIdx.x;
    const float* r = &g_emax[(long)b * TT];
    float s = 0.f;
    for (int t = tid; t < TT; t += 256) s += r[t];
    s = warpSum(s);
    if ((tid & 31) == 0) red[tid >> 5] = s;
    __syncthreads();
    if (tid < 8) {
        float v = red[tid];
#pragma unroll
        for (int o = 4; o > 0; o >>= 1) v += __shfl_xor_sync(0xff, v, o);
        if (tid == 0) g_emaxsum[b] = v;
    }
}

// ---------------------------------------------------------------------------
// Kernel 4: speculative chunked forward scan.
// warp = (batch b, chunk c). Chunk c owns steps [c*128+1, (c+1)*128] (last
// chunk capped at 4095). For c>0 a 64-step burn-in starting from the all-ones
// vector converges to the true normalized state (Hilbert contraction ~0.46^64),
// so per-chunk log factors telescope to the exact logZ within ~1e-20.
// ---------------------------------------------------------------------------
__global__ void __launch_bounds__(256) hmm_scan_kernel() {
    int gw = (blockIdx.x * blockDim.x + threadIdx.x) >> 5;
    int k = threadIdx.x & 31;
    int b = gw >> 5;             // / CC
    int c = gw & (CC - 1);       // % CC
    const float* __restrict__ erow = &g_eexp[(long)b * TT * KK];

    float Acol[KK];
#pragma unroll
    for (int j = 0; j < KK; ++j) Acol[j] = g_expA[j * KK + k];

    float u;
    int t, nburn;
    if (c == 0) { u = g_pi[k] * erow[k]; t = 1; nburn = 0; }
    else        { u = 1.0f; t = c * CHUNK - WARM + 1; nburn = WARM / 16; }
    int tlimit = (c == CC - 1) ? TT : 0x7fffffff;   // last chunk ends at 4095
    int nblk = nburn + CHUNK / 16;                  // 8 or 12 blocks of 16 steps

    float logZ = 0.f;
    float bufA[16], bufB[16];
#pragma unroll
    for (int i = 0; i < 16; ++i) bufA[i] = erow[(long)(t + i) * KK + k];

    for (int blk = 0; blk < nblk; ++blk) {
        int tn = t + 16;
#pragma unroll
        for (int i = 0; i < 16; ++i) {
            int tt = tn + i;
            bufB[i] = (tt < TT) ? erow[(long)tt * KK + k] : 0.f;
        }
        bool burn = (blk < nburn);
#pragma unroll
        for (int i = 0; i < 16; ++i) {
            float s0 = 0.f, s1 = 0.f, s2 = 0.f, s3 = 0.f;
#pragma unroll
            for (int j = 0; j < KK; j += 4) {
                s0 = fmaf(__shfl_sync(FULLMASK, u, j + 0), Acol[j + 0], s0);
                s1 = fmaf(__shfl_sync(FULLMASK, u, j + 1), Acol[j + 1], s1);
                s2 = fmaf(__shfl_sync(FULLMASK, u, j + 2), Acol[j + 2], s2);
                s3 = fmaf(__shfl_sync(FULLMASK, u, j + 3), Acol[j + 3], s3);
            }
            float un = bufA[i] * ((s0 + s1) + (s2 + s3));
            u = (t + i < tlimit) ? un : u;          // tail guard (last chunk only)
        }
        if (t + 15 < tlimit) {                      // block-end renorm
            float S = warpSum(u);
            u = u / S;
            if (!burn) logZ += __logf(S);           // burn-in renorms are discarded
        }
        t = tn;
#pragma unroll
        for (int i = 0; i < 16; ++i) bufA[i] = bufB[i];
    }
    float S = warpSum(u);
    if (k == 0) g_partial2[b * CC + c] = logZ + __logf(S);
}

// ---------------------------------------------------------------------------
// Kernel 5: final scalar (2048 chunk factors + 64 emax sums)
// ---------------------------------------------------------------------------
__global__ void hmm_final_kernel(float* __restrict__ out) {
    __shared__ double red[8];
    int tid = threadIdx.x;
    double v = 0.0;
    for (int i = tid; i < BB * CC; i += 256) v += (double)g_partial2[i];
    for (int i = tid; i < BB; i += 256) v += (double)g_emaxsum[i];
#pragma unroll
    for (int o = 16; o > 0; o >>= 1) v += __shfl_xor_sync(FULLMASK, v, o);
    if ((tid & 31) == 0) red[tid >> 5] = v;
    __syncthreads();
    if (tid < 8) {
        double w = red[tid];
#pragma unroll
        for (int o = 4; o > 0; o >>= 1) w += __shfl_xor_sync(0xff, w, o);
        if (tid == 0) out[0] = (float)w;
    }
}

// ---------------------------------------------------------------------------
extern "C" void kernel_launch(void* const* d_in, const int* in_sizes, int n_in,
                              void* d_out, int out_size) {
    const float* X = (const float*)d_in[0];
    const float* sp = (const float*)d_in[1];
    const float* trans = (const float*)d_in[2];
    const float* mu = (const float*)d_in[3];
    const float* log_var = (const float*)d_in[4];

    hmm_prep_kernel<<<1, 1024>>>(sp, trans, mu, log_var);
    hmm_emis_kernel<<<(BB * TT) / TILE_T2, 256>>>(X);
    hmm_emaxsum_kernel<<<BB, 256>>>();
    hmm_scan_kernel<<<(BB * CC * 32) / 256, 256>>>();
    hmm_final_kernel<<<1, 256>>>((float*)d_out);
}

// round 4
// speedup vs baseline: 19.8760x; 1.9458x over previous
#include <cuda_runtime.h>
#include <math.h>
#include <stdint.h>

#define BB 64
#define TT 4096
#define DD 90
#define KK 32
#define CC 32            // chunks per batch
#define CHUNK 128        // TT / CC
#define WARM 32          // burn-in steps (contraction <=0.762^32 ~ 1.6e-4)
#define LOG2PI_F 1.8378770664093453f
#define FULLMASK 0xffffffffu
#define KPAD 192         // padded GEMM K dim: [x(96) | x^2(96)]
#define NCB 12           // col-blocks of 8 in the x region

// ---- scratch (__device__ globals; no allocations allowed) ----
__device__ __align__(16) float g_eexp[BB * TT * KK];     // exp(em - emax)
__device__ float g_emax[BB * TT];
__device__ float g_emaxsum[BB];
__device__ __align__(16) float2 g_Wp[24 * KK * 4];       // B fragments, tf32-rounded
__device__ __align__(16) float g_bias[KK];
__device__ float g_pi[KK];
__device__ float g_expA[KK * KK];
__device__ float g_partial2[BB * CC];

__device__ __forceinline__ float warpMax(float v) {
#pragma unroll
    for (int o = 16; o > 0; o >>= 1) v = fmaxf(v, __shfl_xor_sync(FULLMASK, v, o));
    return v;
}
__device__ __forceinline__ float warpSum(float v) {
#pragma unroll
    for (int o = 16; o > 0; o >>= 1) v += __shfl_xor_sync(FULLMASK, v, o);
    return v;
}
__device__ __forceinline__ uint32_t f2tf32(float x) {
    uint32_t r;
    asm("cvt.rna.tf32.f32 %0, %1;" : "=r"(r) : "f"(x));
    return r;
}
__device__ __forceinline__ void mma_tf32(float& d0, float& d1, float& d2, float& d3,
                                         uint32_t a0, uint32_t a1, uint32_t a2, uint32_t a3,
                                         uint32_t b0, uint32_t b1) {
    asm volatile("mma.sync.aligned.m16n8k8.row.col.f32.tf32.tf32.f32 "
                 "{%0,%1,%2,%3},{%4,%5,%6,%7},{%8,%9},{%0,%1,%2,%3};"
                 : "+f"(d0), "+f"(d1), "+f"(d2), "+f"(d3)
                 : "r"(a0), "r"(a1), "r"(a2), "r"(a3), "r"(b0), "r"(b1));
}

// ---------------------------------------------------------------------------
// Kernel 1: prep — softmaxes, bias, tf32 B-fragment table
// W(row, k): rows 0..89 = mu*iv (x coeff), 96..185 = -0.5*iv (x^2), else 0.
// Fragment pair p=(c,n,tig): { W[c*8+tig][n], W[c*8+tig+4][n] }
// ---------------------------------------------------------------------------
__global__ void hmm_prep_kernel(const float* __restrict__ sp,
                                const float* __restrict__ trans,
                                const float* __restrict__ mu,
                                const float* __restrict__ log_var) {
    int tid = threadIdx.x, wid = tid >> 5, lane = tid & 31;

    if (wid == 0) {
        float v = sp[lane];
        float m = warpMax(v);
        float e = expf(v - m);
        float s = warpSum(e);
        g_pi[lane] = e / s;
    }
    {
        float v = trans[wid * KK + lane];
        float m = warpMax(v);
        float e = expf(v - m);
        float s = warpSum(e);
        g_expA[wid * KK + lane] = e / s;
    }
    // B fragment table (24 ksteps x 32 n x 4 tig)
    for (int p = tid; p < 24 * KK * 4; p += blockDim.x) {
        int c = p >> 7;
        int rem = p & 127;
        int n = rem >> 2;
        int tig = rem & 3;
        float v[2];
#pragma unroll
        for (int h = 0; h < 2; ++h) {
            int row = c * 8 + tig + h * 4;
            float w = 0.f;
            if (row < 96) {
                int d = row;
                if (d < DD) w = mu[n * DD + d] * expf(-log_var[n * DD + d]);
            } else {
                int d = row - 96;
                if (d < DD) w = -0.5f * expf(-log_var[n * DD + d]);
            }
            v[h] = __uint_as_float(f2tf32(w));
        }
        g_Wp[p] = make_float2(v[0], v[1]);
    }
    // bias
    {
        int k = wid;
        float acc = 0.0f;
        for (int d = lane; d < DD; d += 32) {
            float lv = log_var[k * DD + d];
            float iv = expf(-lv);
            float m = mu[k * DD + d];
            acc = fmaf(m * m, iv, acc + lv);
        }
        acc = warpSum(acc);
        if (lane == 0) g_bias[k] = -0.5f * (acc + (float)DD * LOG2PI_F);
    }
}

// ---------------------------------------------------------------------------
// Kernel 2: emissions via tf32 tensor cores.
// block = 256 thr (8 warps), tile = 128 rows x 32 states. warp tile = 16 x 32.
// A fragments loaded from global (raw X), squared in-register for kstep c+12.
// ---------------------------------------------------------------------------
__global__ void __launch_bounds__(256) hmm_emis_kernel(const float* __restrict__ X) {
    __shared__ __align__(16) float2 ws[24 * KK * 4];   // 24 KB
    __shared__ __align__(8) float sbias[KK];

    int tid = threadIdx.x;
    int wid = tid >> 5, lane = tid & 31;
    int gid = lane >> 2, tig = lane & 3;

    {   // stage fragment table + bias
        const float4* src = (const float4*)g_Wp;
        float4* dst = (float4*)ws;
#pragma unroll
        for (int i = 0; i < 6; ++i) dst[tid + 256 * i] = src[tid + 256 * i];
        if (tid < KK) sbias[tid] = g_bias[tid];
    }
    __syncthreads();

    long rowbase = (long)blockIdx.x * 128 + wid * 16;
    const float* xr0 = X + (rowbase + gid) * DD;
    const float* xr1 = X + (rowbase + gid + 8) * DD;

    float acc[4][4];
#pragma unroll
    for (int nt = 0; nt < 4; ++nt)
#pragma unroll
        for (int i = 0; i < 4; ++i) acc[nt][i] = 0.f;

#pragma unroll
    for (int cb = 0; cb < NCB; ++cb) {
        int col0 = cb * 8 + tig;
        int col1 = col0 + 4;
        float x0 = (col0 < DD) ? xr0[col0] : 0.f;
        float x1 = (col0 < DD) ? xr1[col0] : 0.f;
        float x2 = (col1 < DD) ? xr0[col1] : 0.f;
        float x3 = (col1 < DD) ? xr1[col1] : 0.f;
        uint32_t a0 = f2tf32(x0), a1 = f2tf32(x1), a2 = f2tf32(x2), a3 = f2tf32(x3);
        float f0 = __uint_as_float(a0), f1 = __uint_as_float(a1);
        float f2v = __uint_as_float(a2), f3 = __uint_as_float(a3);
        uint32_t s0 = f2tf32(f0 * f0), s1 = f2tf32(f1 * f1);
        uint32_t s2 = f2tf32(f2v * f2v), s3 = f2tf32(f3 * f3);
#pragma unroll
        for (int nt = 0; nt < 4; ++nt) {
            float2 b = ws[(cb * KK + nt * 8 + gid) * 4 + tig];
            mma_tf32(acc[nt][0], acc[nt][1], acc[nt][2], acc[nt][3],
                     a0, a1, a2, a3, __float_as_uint(b.x), __float_as_uint(b.y));
        }
#pragma unroll
        for (int nt = 0; nt < 4; ++nt) {
            float2 b = ws[((cb + NCB) * KK + nt * 8 + gid) * 4 + tig];
            mma_tf32(acc[nt][0], acc[nt][1], acc[nt][2], acc[nt][3],
                     s0, s1, s2, s3, __float_as_uint(b.x), __float_as_uint(b.y));
        }
    }

    // epilogue: +bias, row max over k, exp, store
    const float2* sb2 = (const float2*)sbias;
    float m0 = -1e30f, m1 = -1e30f;
#pragma unroll
    for (int nt = 0; nt < 4; ++nt) {
        float2 bv = sb2[nt * 4 + tig];
        acc[nt][0] += bv.x; acc[nt][1] += bv.y;
        acc[nt][2] += bv.x; acc[nt][3] += bv.y;
        m0 = fmaxf(m0, fmaxf(acc[nt][0], acc[nt][1]));
        m1 = fmaxf(m1, fmaxf(acc[nt][2], acc[nt][3]));
    }
#pragma unroll
    for (int o = 1; o <= 2; o <<= 1) {
        m0 = fmaxf(m0, __shfl_xor_sync(FULLMASK, m0, o));
        m1 = fmaxf(m1, __shfl_xor_sync(FULLMASK, m1, o));
    }
    long bt0 = rowbase + gid, bt1 = bt0 + 8;
#pragma unroll
    for (int nt = 0; nt < 4; ++nt) {
        float2 e0, e1;
        e0.x = __expf(acc[nt][0] - m0); e0.y = __expf(acc[nt][1] - m0);
        e1.x = __expf(acc[nt][2] - m1); e1.y = __expf(acc[nt][3] - m1);
        *(float2*)&g_eexp[bt0 * KK + nt * 8 + tig * 2] = e0;
        *(float2*)&g_eexp[bt1 * KK + nt * 8 + tig * 2] = e1;
    }
    if (tig == 0) { g_emax[bt0] = m0; g_emax[bt1] = m1; }
}

// ---------------------------------------------------------------------------
// Kernel 3: per-batch sum of emax
// ---------------------------------------------------------------------------
__global__ void hmm_emaxsum_kernel() {
    __shared__ float red[8];
    int b = blockIdx.x, tid = threadIdx.x;
    const float* r = &g_emax[(long)b * TT];
    float s = 0.f;
    for (int t = tid; t < TT; t += 256) s += r[t];
    s = warpSum(s);
    if ((tid & 31) == 0) red[tid >> 5] = s;
    __syncthreads();
    if (tid < 8) {
        float v = red[tid];
#pragma unroll
        for (int o = 4; o > 0; o >>= 1) v += __shfl_xor_sync(0xff, v, o);
        if (tid == 0) g_emaxsum[b] = v;
    }
}

// ---------------------------------------------------------------------------
// Kernel 4: speculative chunked forward scan (1 warp per block for balance)
// ---------------------------------------------------------------------------
__global__ void __launch_bounds__(32) hmm_scan_kernel() {
    int gw = blockIdx.x;
    int k = threadIdx.x;
    int b = gw >> 5;             // / CC
    int c = gw & (CC - 1);       // % CC
    const float* __restrict__ erow = &g_eexp[(long)b * TT * KK];

    float Acol[KK];
#pragma unroll
    for (int j = 0; j < KK; ++j) Acol[j] = g_expA[j * KK + k];

    float u;
    int t, nburn;
    if (c == 0) { u = g_pi[k] * erow[k]; t = 1; nburn = 0; }
    else        { u = 1.0f; t = c * CHUNK - WARM + 1; nburn = WARM / 16; }
    int tlimit = (c == CC - 1) ? TT : 0x7fffffff;
    int nblk = nburn + CHUNK / 16;

    float logZ = 0.f;
    float bufA[16], bufB[16];
#pragma unroll
    for (int i = 0; i < 16; ++i) bufA[i] = erow[(long)(t + i) * KK + k];

    for (int blk = 0; blk < nblk; ++blk) {
        int tn = t + 16;
#pragma unroll
        for (int i = 0; i < 16; ++i) {
            int tt = tn + i;
            bufB[i] = (tt < TT) ? erow[(long)tt * KK + k] : 0.f;
        }
        bool burn = (blk < nburn);
#pragma unroll
        for (int i = 0; i < 16; ++i) {
            float s0 = 0.f, s1 = 0.f, s2 = 0.f, s3 = 0.f;
#pragma unroll
            for (int j = 0; j < KK; j += 4) {
                s0 = fmaf(__shfl_sync(FULLMASK, u, j + 0), Acol[j + 0], s0);
                s1 = fmaf(__shfl_sync(FULLMASK, u, j + 1), Acol[j + 1], s1);
                s2 = fmaf(__shfl_sync(FULLMASK, u, j + 2), Acol[j + 2], s2);
                s3 = fmaf(__shfl_sync(FULLMASK, u, j + 3), Acol[j + 3], s3);
            }
            float un = bufA[i] * ((s0 + s1) + (s2 + s3));
            u = (t + i < tlimit) ? un : u;
        }
        if (t + 15 < tlimit) {
            float S = warpSum(u);
            u = u / S;
            if (!burn) logZ += __logf(S);
        }
        t = tn;
#pragma unroll
        for (int i = 0; i < 16; ++i) bufA[i] = bufB[i];
    }
    float S = warpSum(u);
    if (k == 0) g_partial2[b * CC + c] = logZ + __logf(S);
}

// ---------------------------------------------------------------------------
// Kernel 5: final scalar
// ---------------------------------------------------------------------------
__global__ void hmm_final_kernel(float* __restrict__ out) {
    __shared__ double red[8];
    int tid = threadIdx.x;
    double v = 0.0;
    for (int i = tid; i < BB * CC; i += 256) v += (double)g_partial2[i];
    for (int i = tid; i < BB; i += 256) v += (double)g_emaxsum[i];
#pragma unroll
    for (int o = 16; o > 0; o >>= 1) v += __shfl_xor_sync(FULLMASK, v, o);
    if ((tid & 31) == 0) red[tid >> 5] = v;
    __syncthreads();
    if (tid < 8) {
        double w = red[tid];
#pragma unroll
        for (int o = 4; o > 0; o >>= 1) w += __shfl_xor_sync(0xff, w, o);
        if (tid == 0) out[0] = (float)w;
    }
}

// ---------------------------------------------------------------------------
extern "C" void kernel_launch(void* const* d_in, const int* in_sizes, int n_in,
                              void* d_out, int out_size) {
    const float* X = (const float*)d_in[0];
    const float* sp = (const float*)d_in[1];
    const float* trans = (const float*)d_in[2];
    const float* mu = (const float*)d_in[3];
    const float* log_var = (const float*)d_in[4];

    hmm_prep_kernel<<<1, 1024>>>(sp, trans, mu, log_var);
    hmm_emis_kernel<<<(BB * TT) / 128, 256>>>(X);
    hmm_emaxsum_kernel<<<BB, 256>>>();
    hmm_scan_kernel<<<BB * CC, 32>>>();
    hmm_final_kernel<<<1, 256>>>((float*)d_out);
}

// round 5
// speedup vs baseline: 25.4806x; 1.2820x over previous
#include <cuda_runtime.h>
#include <cuda_bf16.h>
#include <math.h>
#include <stdint.h>

#define BB 64
#define TT 4096
#define DD 90
#define KK 32
#define CC 32            // chunks per batch
#define CHUNK 128        // TT / CC
#define WARM 32          // burn-in steps (Birkhoff contraction <=0.762^32 ~ 1.6e-4)
#define LOG2PI_F 1.8378770664093453f
#define FULLMASK 0xffffffffu

// ---- scratch (__device__ globals; no allocations allowed) ----
__device__ __align__(16) float g_eexp[BB * TT * KK];     // exp(em - emax)
__device__ float g_emax[BB * TT];
__device__ float g_emaxsum[BB];
__device__ __align__(16) uint2 g_Wb[12 * 4 * 32];        // bf16 B-fragment table
__device__ __align__(16) float g_bias[KK];
__device__ float g_pi[KK];
__device__ float g_expA[KK * KK];
__device__ float g_partial2[BB * CC];

__device__ __forceinline__ float warpMax(float v) {
#pragma unroll
    for (int o = 16; o > 0; o >>= 1) v = fmaxf(v, __shfl_xor_sync(FULLMASK, v, o));
    return v;
}
__device__ __forceinline__ float warpSum(float v) {
#pragma unroll
    for (int o = 16; o > 0; o >>= 1) v += __shfl_xor_sync(FULLMASK, v, o);
    return v;
}
__device__ __forceinline__ uint32_t packbf2(float lo, float hi) {
    __nv_bfloat162 h = __floats2bfloat162_rn(lo, hi);   // .x = lo
    return *reinterpret_cast<uint32_t*>(&h);
}
__device__ __forceinline__ void mma_bf16(float& d0, float& d1, float& d2, float& d3,
                                         uint32_t a0, uint32_t a1, uint32_t a2, uint32_t a3,
                                         uint32_t b0, uint32_t b1) {
    asm volatile("mma.sync.aligned.m16n8k16.row.col.f32.bf16.bf16.f32 "
                 "{%0,%1,%2,%3},{%4,%5,%6,%7},{%8,%9},{%0,%1,%2,%3};"
                 : "+f"(d0), "+f"(d1), "+f"(d2), "+f"(d3)
                 : "r"(a0), "r"(a1), "r"(a2), "r"(a3), "r"(b0), "r"(b1));
}

// ---------------------------------------------------------------------------
// Kernel 1: prep — softmaxes, bias, bf16 B-fragment table.
// Logical GEMM: em = [x(96) | x^2(96)] (KPAD=192) @ W(192x32). 12 ksteps of 16.
// Fragment p = (s, nt, lane): b0 = {W[s*16+tig*2][n], W[..+1][n]},
//                             b1 = {W[s*16+tig*2+8][n], W[..+9][n]}, n = nt*8+gid.
// ---------------------------------------------------------------------------
__global__ void hmm_prep_kernel(const float* __restrict__ sp,
                                const float* __restrict__ trans,
                                const float* __restrict__ mu,
                                const float* __restrict__ log_var) {
    int tid = threadIdx.x, wid = tid >> 5, lane = tid & 31;

    if (wid == 0) {
        float v = sp[lane];
        float m = warpMax(v);
        float e = expf(v - m);
        float s = warpSum(e);
        g_pi[lane] = e / s;
    }
    {
        float v = trans[wid * KK + lane];
        float m = warpMax(v);
        float e = expf(v - m);
        float s = warpSum(e);
        g_expA[wid * KK + lane] = e / s;
    }
    for (int p = tid; p < 12 * 4 * 32; p += blockDim.x) {
        int s = p >> 7;
        int rem = p & 127;
        int ln = rem & 31;
        int gid = ln >> 2, tig = ln & 3;
        int n = (rem >> 5) * 8 + gid;
        float w[4];
#pragma unroll
        for (int h = 0; h < 4; ++h) {
            int row = s * 16 + tig * 2 + (h >> 1) * 8 + (h & 1);
            float v = 0.f;
            if (row < 96) {
                int d = row;
                if (d < DD) v = mu[n * DD + d] * expf(-log_var[n * DD + d]);
            } else {
                int d = row - 96;
                if (d < DD) v = -0.5f * expf(-log_var[n * DD + d]);
            }
            w[h] = v;
        }
        g_Wb[p] = make_uint2(packbf2(w[0], w[1]), packbf2(w[2], w[3]));
    }
    {
        int k = wid;
        float acc = 0.0f;
        for (int d = lane; d < DD; d += 32) {
            float lv = log_var[k * DD + d];
            float iv = expf(-lv);
            float m = mu[k * DD + d];
            acc = fmaf(m * m, iv, acc + lv);
        }
        acc = warpSum(acc);
        if (lane == 0) g_bias[k] = -0.5f * (acc + (float)DD * LOG2PI_F);
    }
}

// ---------------------------------------------------------------------------
// Kernel 2: emissions via bf16 m16n8k16 tensor cores.
// block = 256 thr (8 warps), tile = 128 rows x 32 states; warp tile 16 x 32.
// 6 iterations: x k-step + x^2 k-step (squares computed in-register).
// ---------------------------------------------------------------------------
__global__ void __launch_bounds__(256) hmm_emis_kernel(const float* __restrict__ X) {
    __shared__ __align__(16) uint2 ws[12 * 4 * 32];   // 12 KB
    __shared__ __align__(8) float sbias[KK];

    int tid = threadIdx.x;
    int wid = tid >> 5, lane = tid & 31;
    int gid = lane >> 2, tig = lane & 3;

    {
        const uint4* src = (const uint4*)g_Wb;
        uint4* dst = (uint4*)ws;
#pragma unroll
        for (int i = 0; i < 3; ++i) dst[tid + 256 * i] = src[tid + 256 * i];
        if (tid < KK) sbias[tid] = g_bias[tid];
    }
    __syncthreads();

    long rowbase = (long)blockIdx.x * 128 + wid * 16;
    const float* xr0 = X + (rowbase + gid) * DD;
    const float* xr1 = xr0 + 8 * DD;

    float acc[4][4];
#pragma unroll
    for (int nt = 0; nt < 4; ++nt)
#pragma unroll
        for (int i = 0; i < 4; ++i) acc[nt][i] = 0.f;

#pragma unroll
    for (int s = 0; s < 6; ++s) {
        int c0 = s * 16 + tig * 2;
        int c1 = c0 + 8;
        float2 z = make_float2(0.f, 0.f);
        float2 f00 = (c0 < DD) ? *(const float2*)(xr0 + c0) : z;
        float2 f10 = (c0 < DD) ? *(const float2*)(xr1 + c0) : z;
        float2 f01 = (c1 < DD) ? *(const float2*)(xr0 + c1) : z;
        float2 f11 = (c1 < DD) ? *(const float2*)(xr1 + c1) : z;
        uint32_t a0 = packbf2(f00.x, f00.y), a1 = packbf2(f10.x, f10.y);
        uint32_t a2 = packbf2(f01.x, f01.y), a3 = packbf2(f11.x, f11.y);
        uint32_t q0 = packbf2(f00.x * f00.x, f00.y * f00.y);
        uint32_t q1 = packbf2(f10.x * f10.x, f10.y * f10.y);
        uint32_t q2 = packbf2(f01.x * f01.x, f01.y * f01.y);
        uint32_t q3 = packbf2(f11.x * f11.x, f11.y * f11.y);
#pragma unroll
        for (int nt = 0; nt < 4; ++nt) {
            uint2 bb = ws[(s * 4 + nt) * 32 + lane];
            mma_bf16(acc[nt][0], acc[nt][1], acc[nt][2], acc[nt][3],
                     a0, a1, a2, a3, bb.x, bb.y);
        }
#pragma unroll
        for (int nt = 0; nt < 4; ++nt) {
            uint2 bb = ws[((s + 6) * 4 + nt) * 32 + lane];
            mma_bf16(acc[nt][0], acc[nt][1], acc[nt][2], acc[nt][3],
                     q0, q1, q2, q3, bb.x, bb.y);
        }
    }

    // epilogue: +bias, row max over k, exp, store
    const float2* sb2 = (const float2*)sbias;
    float m0 = -1e30f, m1 = -1e30f;
#pragma unroll
    for (int nt = 0; nt < 4; ++nt) {
        float2 bv = sb2[nt * 4 + tig];
        acc[nt][0] += bv.x; acc[nt][1] += bv.y;
        acc[nt][2] += bv.x; acc[nt][3] += bv.y;
        m0 = fmaxf(m0, fmaxf(acc[nt][0], acc[nt][1]));
        m1 = fmaxf(m1, fmaxf(acc[nt][2], acc[nt][3]));
    }
#pragma unroll
    for (int o = 1; o <= 2; o <<= 1) {
        m0 = fmaxf(m0, __shfl_xor_sync(FULLMASK, m0, o));
        m1 = fmaxf(m1, __shfl_xor_sync(FULLMASK, m1, o));
    }
    long bt0 = rowbase + gid, bt1 = bt0 + 8;
#pragma unroll
    for (int nt = 0; nt < 4; ++nt) {
        float2 e0, e1;
        e0.x = __expf(acc[nt][0] - m0); e0.y = __expf(acc[nt][1] - m0);
        e1.x = __expf(acc[nt][2] - m1); e1.y = __expf(acc[nt][3] - m1);
        *(float2*)&g_eexp[bt0 * KK + nt * 8 + tig * 2] = e0;
        *(float2*)&g_eexp[bt1 * KK + nt * 8 + tig * 2] = e1;
    }
    if (tig == 0) { g_emax[bt0] = m0; g_emax[bt1] = m1; }
}

// ---------------------------------------------------------------------------
// Kernel 3: per-batch sum of emax
// ---------------------------------------------------------------------------
__global__ void hmm_emaxsum_kernel() {
    __shared__ float red[8];
    int b = blockIdx.x, tid = threadIdx.x;
    const float* r = &g_emax[(long)b * TT];
    float s = 0.f;
    for (int t = tid; t < TT; t += 256) s += r[t];
    s = warpSum(s);
    if ((tid & 31) == 0) red[tid >> 5] = s;
    __syncthreads();
    if (tid < 8) {
        float v = red[tid];
#pragma unroll
        for (int o = 4; o > 0; o >>= 1) v += __shfl_xor_sync(0xff, v, o);
        if (tid == 0) g_emaxsum[b] = v;
    }
}

// ---------------------------------------------------------------------------
// Kernel 4: speculative chunked scan, 2 chains per warp.
// Lanes 0-15 = chain (b, 2*cp), lanes 16-31 = chain (b, 2*cp+1).
// Each lane holds states 2*hl, 2*hl+1 of its chain; width-16 shuffles
// broadcast both chains simultaneously -> SHFL per chain-step halves.
// Uniform 20-block loop (4 burn + 16 useful blocks of 8 steps); c==0 lanes
// freeze during the burn window, c==CC-1 lanes freeze past t=4095.
// ---------------------------------------------------------------------------
__global__ void __launch_bounds__(64) hmm_scan_kernel() {
    int w = blockIdx.x * 2 + (threadIdx.x >> 5);   // 0 .. BB*CC/2-1
    int lane = threadIdx.x & 31;
    int half = lane >> 4;
    int hl = lane & 15;
    int b = w >> 4;                // 16 chain-pairs per batch
    int cp = w & 15;
    int c = cp * 2 + half;
    int k0 = hl * 2;
    const float* __restrict__ erow = g_eexp + (long)b * TT * KK;

    float A0[KK], A1[KK];
#pragma unroll
    for (int j = 0; j < KK; ++j) {
        A0[j] = g_expA[j * KK + k0];
        A1[j] = g_expA[j * KK + k0 + 1];
    }

    int tstart = c * CHUNK - WARM + 1;                 // c=0 -> -31
    int tmin = (c == 0) ? 1 : tstart;
    int tmax = (c == CC - 1) ? (TT - 1) : (c + 1) * CHUNK;
    float u0, u1;
    if (c == 0) { u0 = g_pi[k0] * erow[k0]; u1 = g_pi[k0 + 1] * erow[k0 + 1]; }
    else        { u0 = 1.f; u1 = 1.f; }

    float logZ = 0.f;
    float2 bufA[8], bufB[8];
#pragma unroll
    for (int i = 0; i < 8; ++i) {
        int tc = tstart + i; tc = tc < 0 ? 0 : tc;
        bufA[i] = *(const float2*)&erow[(long)tc * KK + k0];
    }

    for (int blk = 0; blk < 20; ++blk) {
        int tb = tstart + blk * 8;
#pragma unroll
        for (int i = 0; i < 8; ++i) {
            int tc = tb + 8 + i;
            tc = tc < 0 ? 0 : (tc > TT - 1 ? TT - 1 : tc);
            bufB[i] = *(const float2*)&erow[(long)tc * KK + k0];
        }
#pragma unroll
        for (int i = 0; i < 8; ++i) {
            int t = tb + i;
            float s0a = 0.f, s0b = 0.f, s1a = 0.f, s1b = 0.f;
#pragma unroll
            for (int jj = 0; jj < 16; ++jj) {
                float bu0 = __shfl_sync(FULLMASK, u0, jj, 16);
                float bu1 = __shfl_sync(FULLMASK, u1, jj, 16);
                s0a = fmaf(bu0, A0[2 * jj], s0a);
                s1a = fmaf(bu0, A1[2 * jj], s1a);
                s0b = fmaf(bu1, A0[2 * jj + 1], s0b);
                s1b = fmaf(bu1, A1[2 * jj + 1], s1b);
            }
            bool v = (t >= tmin) && (t <= tmax);
            float n0 = bufA[i].x * (s0a + s0b);
            float n1 = bufA[i].y * (s1a + s1b);
            u0 = v ? n0 : u0;
            u1 = v ? n1 : u1;
        }
        float S = u0 + u1;
#pragma unroll
        for (int o = 1; o <= 8; o <<= 1) S += __shfl_xor_sync(FULLMASK, S, o);
        bool doLog = (blk >= WARM / 8);
        bool doRen = doLog || (c != 0);
        if (doRen) { u0 /= S; u1 /= S; }
        if (doLog) logZ += __logf(S);
#pragma unroll
        for (int i = 0; i < 8; ++i) bufA[i] = bufB[i];
    }
    float S = u0 + u1;
#pragma unroll
    for (int o = 1; o <= 8; o <<= 1) S += __shfl_xor_sync(FULLMASK, S, o);
    if (hl == 0) g_partial2[b * CC + c] = logZ + __logf(S);
}

// ---------------------------------------------------------------------------
// Kernel 5: final scalar
// ---------------------------------------------------------------------------
__global__ void hmm_final_kernel(float* __restrict__ out) {
    __shared__ double red[8];
    int tid = threadIdx.x;
    double v = 0.0;
    for (int i = tid; i < BB * CC; i += 256) v += (double)g_partial2[i];
    for (int i = tid; i < BB; i += 256) v += (double)g_emaxsum[i];
#pragma unroll
    for (int o = 16; o > 0; o >>= 1) v += __shfl_xor_sync(FULLMASK, v, o);
    if ((tid & 31) == 0) red[tid >> 5] = v;
    __syncthreads();
    if (tid < 8) {
        double w = red[tid];
#pragma unroll
        for (int o = 4; o > 0; o >>= 1) w += __shfl_xor_sync(0xff, w, o);
        if (tid == 0) out[0] = (float)w;
    }
}

// ---------------------------------------------------------------------------
extern "C" void kernel_launch(void* const* d_in, const int* in_sizes, int n_in,
                              void* d_out, int out_size) {
    const float* X = (const float*)d_in[0];
    const float* sp = (const float*)d_in[1];
    const float* trans = (const float*)d_in[2];
    const float* mu = (const float*)d_in[3];
    const float* log_var = (const float*)d_in[4];

    hmm_prep_kernel<<<1, 1024>>>(sp, trans, mu, log_var);
    hmm_emis_kernel<<<(BB * TT) / 128, 256>>>(X);
    hmm_emaxsum_kernel<<<BB, 256>>>();
    hmm_scan_kernel<<<BB * CC / 4, 64>>>();
    hmm_final_kernel<<<1, 256>>>((float*)d_out);
}